// round 1
// baseline (speedup 1.0000x reference)
#include <cuda_runtime.h>
#include <stdint.h>

#define N_NODES   100000
#define N_EDGES   1600000
#define D         128
#define N_LAYERS  3
#define N_CLASSES 10
#define N_GRAPHS  512
#define BN_EPS    1e-5f

// ---------------------------------------------------------------------------
// Static device scratch (allocation-free rule: __device__ globals only)
// ---------------------------------------------------------------------------
__device__ float g_bufA[(size_t)N_NODES * D];   // 51.2 MB
__device__ float g_bufB[(size_t)N_NODES * D];   // 51.2 MB
__device__ int   g_deg[N_NODES];
__device__ int   g_off[N_NODES + 1];
__device__ int   g_cur[N_NODES];
__device__ int   g_csr[N_EDGES];
__device__ float g_sum[D];
__device__ float g_sumsq[D];
__device__ float g_scale[D];
__device__ float g_shift[D];
__device__ float g_pool[N_GRAPHS * D];
__device__ float g_cnt[N_GRAPHS];

// ---------------------------------------------------------------------------
// Packed f32x2 helpers (sm_100+: fma.rn.f32x2 — 2x fp32 FMA rate)
// ---------------------------------------------------------------------------
__device__ __forceinline__ unsigned long long pack2(float x) {
    unsigned long long r;
    unsigned int u = __float_as_uint(x);
    asm("mov.b64 %0, {%1, %1};" : "=l"(r) : "r"(u));
    return r;
}
__device__ __forceinline__ unsigned long long ffma2(unsigned long long a,
                                                    unsigned long long b,
                                                    unsigned long long c) {
    unsigned long long d;
    asm("fma.rn.f32x2 %0, %1, %2, %3;" : "=l"(d) : "l"(a), "l"(b), "l"(c));
    return d;
}
__device__ __forceinline__ void unpack2(unsigned long long v, float& lo, float& hi) {
    unsigned int a, b;
    asm("mov.b64 {%0, %1}, %2;" : "=r"(a), "=r"(b) : "l"(v));
    lo = __uint_as_float(a);
    hi = __uint_as_float(b);
}

// ---------------------------------------------------------------------------
// CSR build
// ---------------------------------------------------------------------------
__global__ void zero_deg_kernel() {
    for (int i = blockIdx.x * blockDim.x + threadIdx.x; i < N_NODES;
         i += gridDim.x * blockDim.x)
        g_deg[i] = 0;
}

__global__ void hist_kernel(const int* __restrict__ dstA) {
    for (int e = blockIdx.x * blockDim.x + threadIdx.x; e < N_EDGES;
         e += gridDim.x * blockDim.x)
        atomicAdd(&g_deg[dstA[e]], 1);
}

__global__ void scan_kernel() {
    const int T = 1024;
    const int chunk = (N_NODES + T - 1) / T;  // 98
    int tid = threadIdx.x;
    int lo = tid * chunk;
    int hi = lo + chunk;
    if (hi > N_NODES) hi = N_NODES;
    if (lo > N_NODES) lo = N_NODES;

    int s = 0;
    for (int i = lo; i < hi; i++) s += g_deg[i];

    __shared__ int sm[T];
    sm[tid] = s;
    __syncthreads();
    for (int off = 1; off < T; off <<= 1) {
        int v = (tid >= off) ? sm[tid - off] : 0;
        __syncthreads();
        sm[tid] += v;
        __syncthreads();
    }
    int run = (tid == 0) ? 0 : sm[tid - 1];
    for (int i = lo; i < hi; i++) {
        g_off[i] = run;
        g_cur[i] = run;
        run += g_deg[i];
    }
    if (tid == T - 1) g_off[N_NODES] = run;
}

__global__ void fill_kernel(const int* __restrict__ srcA,
                            const int* __restrict__ dstA) {
    for (int e = blockIdx.x * blockDim.x + threadIdx.x; e < N_EDGES;
         e += gridDim.x * blockDim.x) {
        int p = atomicAdd(&g_cur[dstA[e]], 1);
        g_csr[p] = srcA[e];
    }
}

// ---------------------------------------------------------------------------
// BN-affine init / stats
// ---------------------------------------------------------------------------
__global__ void init_affine_kernel() {
    int t = threadIdx.x;
    if (t < D) { g_scale[t] = 1.0f; g_shift[t] = 0.0f; }
}

__global__ void zero_stats_kernel() {
    int t = threadIdx.x;
    if (t < D) { g_sum[t] = 0.0f; g_sumsq[t] = 0.0f; }
}

__global__ void bn_finalize_kernel(const float* __restrict__ gamma,
                                   const float* __restrict__ beta) {
    int t = threadIdx.x;
    if (t < D) {
        float mu  = g_sum[t]   * (1.0f / (float)N_NODES);
        float var = g_sumsq[t] * (1.0f / (float)N_NODES) - mu * mu;
        if (var < 0.0f) var = 0.0f;
        float inv = rsqrtf(var + BN_EPS);
        float sc  = gamma[t] * inv;
        g_scale[t] = sc;
        g_shift[t] = beta[t] - mu * sc;
    }
}

// ---------------------------------------------------------------------------
// Aggregation: h_pre = scale ⊙ (x_i + Σ_{j->i} x_j) + (1+deg)·shift
//   (scale/shift fold in the previous layer's BatchNorm; identity for layer 0)
// Warp per node, lane owns 4 contiguous features.
// ---------------------------------------------------------------------------
__global__ void __launch_bounds__(256)
aggregate_kernel(const float* __restrict__ xin, float* __restrict__ out) {
    int warp = threadIdx.x >> 5;
    int lane = threadIdx.x & 31;
    int node = blockIdx.x * 8 + warp;
    if (node >= N_NODES) return;
    int c0 = lane * 4;

    float4 acc = *reinterpret_cast<const float4*>(&xin[(size_t)node * D + c0]);
    int s = g_off[node], e = g_off[node + 1];
    int deg = e - s;

    for (int b = s; b < e; b += 32) {
        int idx = 0;
        if (b + lane < e) idx = g_csr[b + lane];
        int m = e - b;
        if (m > 32) m = 32;
        for (int t = 0; t < m; t++) {
            int j = __shfl_sync(0xffffffffu, idx, t);
            float4 v = *reinterpret_cast<const float4*>(&xin[(size_t)j * D + c0]);
            acc.x += v.x; acc.y += v.y; acc.z += v.z; acc.w += v.w;
        }
    }

    float4 sc = *reinterpret_cast<const float4*>(&g_scale[c0]);
    float4 sh = *reinterpret_cast<const float4*>(&g_shift[c0]);
    float dp1 = (float)(deg + 1);
    float4 o;
    o.x = sc.x * acc.x + dp1 * sh.x;
    o.y = sc.y * acc.y + dp1 * sh.y;
    o.z = sc.z * acc.z + dp1 * sh.z;
    o.w = sc.w * acc.w + dp1 * sh.w;
    *reinterpret_cast<float4*>(&out[(size_t)node * D + c0]) = o;
}

// ---------------------------------------------------------------------------
// GEMM: C = relu(A @ W + b), A: N_NODES x 128, W: 128 x 128 (row-major)
// BM=64 rows per block, 256 threads, 4x8 register tile, f32x2 packed FMA.
// STATS=1 additionally accumulates per-column sum / sum-of-squares.
// ---------------------------------------------------------------------------
template <int STATS>
__global__ void __launch_bounds__(256, 2)
gemm_relu(const float* __restrict__ A, const float* __restrict__ Wm,
          const float* __restrict__ bias, float* __restrict__ Cout) {
    extern __shared__ float smem[];
    float* sW   = smem;               // 128*128 = 16384 floats (64 KB)
    float* sA   = smem + D * D;       // 64*132 padded
    float* sSum = sA + 64 * 132;      // 128
    float* sSq  = sSum + D;           // 128

    const int tid  = threadIdx.x;
    const int row0 = blockIdx.x * 64;

    // Load full W into smem
    #pragma unroll
    for (int i = tid * 4; i < D * D; i += 256 * 4)
        *reinterpret_cast<float4*>(&sW[i]) =
            *reinterpret_cast<const float4*>(&Wm[i]);

    // Load A tile (64 x 128), guard tail rows
    for (int i = tid; i < 64 * 32; i += 256) {
        int r = i >> 5, c = (i & 31) << 2;
        int gr = row0 + r;
        float4 v = make_float4(0.f, 0.f, 0.f, 0.f);
        if (gr < N_NODES)
            v = *reinterpret_cast<const float4*>(&A[(size_t)gr * D + c]);
        *reinterpret_cast<float4*>(&sA[r * 132 + c]) = v;
    }
    if (STATS && tid < D) { sSum[tid] = 0.0f; sSq[tid] = 0.0f; }
    __syncthreads();

    const int tx   = tid & 15;
    const int ty   = tid >> 4;
    const int col0 = tx * 8;
    const int r0   = ty * 4;

    unsigned long long acc[4][4];
    #pragma unroll
    for (int r = 0; r < 4; r++)
        #pragma unroll
        for (int c = 0; c < 4; c++) acc[r][c] = 0ull;

    #pragma unroll 4
    for (int k = 0; k < D; k++) {
        unsigned long long av[4];
        #pragma unroll
        for (int r = 0; r < 4; r++) av[r] = pack2(sA[(r0 + r) * 132 + k]);
        unsigned long long wv[4];
        const float* wrow = &sW[k * D + col0];
        #pragma unroll
        for (int c = 0; c < 4; c++)
            wv[c] = *reinterpret_cast<const unsigned long long*>(wrow + 2 * c);
        #pragma unroll
        for (int r = 0; r < 4; r++)
            #pragma unroll
            for (int c = 0; c < 4; c++)
                acc[r][c] = ffma2(av[r], wv[c], acc[r][c]);
    }

    float bv[8];
    #pragma unroll
    for (int c = 0; c < 8; c++) bv[c] = bias[col0 + c];

    float lsum[8], lsq[8];
    if (STATS) {
        #pragma unroll
        for (int c = 0; c < 8; c++) { lsum[c] = 0.0f; lsq[c] = 0.0f; }
    }

    #pragma unroll
    for (int r = 0; r < 4; r++) {
        int gr = row0 + r0 + r;
        if (gr >= N_NODES) break;
        float v[8];
        #pragma unroll
        for (int c = 0; c < 4; c++) {
            float lo, hi;
            unpack2(acc[r][c], lo, hi);
            v[2 * c]     = fmaxf(lo + bv[2 * c], 0.0f);
            v[2 * c + 1] = fmaxf(hi + bv[2 * c + 1], 0.0f);
        }
        #pragma unroll
        for (int c = 0; c < 4; c++) {
            float2 st;
            st.x = v[2 * c];
            st.y = v[2 * c + 1];
            *reinterpret_cast<float2*>(&Cout[(size_t)gr * D + col0 + 2 * c]) = st;
        }
        if (STATS) {
            #pragma unroll
            for (int c = 0; c < 8; c++) {
                lsum[c] += v[c];
                lsq[c]  += v[c] * v[c];
            }
        }
    }

    if (STATS) {
        #pragma unroll
        for (int c = 0; c < 8; c++) {
            atomicAdd(&sSum[col0 + c], lsum[c]);
            atomicAdd(&sSq[col0 + c], lsq[c]);
        }
        __syncthreads();
        if (tid < D) {
            atomicAdd(&g_sum[tid], sSum[tid]);
            atomicAdd(&g_sumsq[tid], sSq[tid]);
        }
    }
}

// ---------------------------------------------------------------------------
// Pooling + MLP head
// ---------------------------------------------------------------------------
__global__ void zero_pool_kernel() {
    int i = blockIdx.x * blockDim.x + threadIdx.x;
    int n = N_GRAPHS * D + N_GRAPHS;
    for (; i < n; i += gridDim.x * blockDim.x) {
        if (i < N_GRAPHS * D) g_pool[i] = 0.0f;
        else g_cnt[i - N_GRAPHS * D] = 0.0f;
    }
}

__global__ void __launch_bounds__(256)
pool_kernel(const float* __restrict__ xin, const int* __restrict__ batch) {
    int warp = threadIdx.x >> 5;
    int lane = threadIdx.x & 31;
    int node = blockIdx.x * 8 + warp;
    if (node >= N_NODES) return;
    int g  = batch[node];
    int c0 = lane * 4;
    float4 v = *reinterpret_cast<const float4*>(&xin[(size_t)node * D + c0]);
    atomicAdd(&g_pool[g * D + c0 + 0], v.x);
    atomicAdd(&g_pool[g * D + c0 + 1], v.y);
    atomicAdd(&g_pool[g * D + c0 + 2], v.z);
    atomicAdd(&g_pool[g * D + c0 + 3], v.w);
    if (lane == 0) atomicAdd(&g_cnt[g], 1.0f);
}

__global__ void head_kernel(const float* __restrict__ lin1w,
                            const float* __restrict__ lin1b,
                            const float* __restrict__ lin2w,
                            const float* __restrict__ lin2b,
                            float* __restrict__ out) {
    __shared__ float row[D];
    __shared__ float hid[D];
    int g = blockIdx.x;
    int t = threadIdx.x;

    float cnt = g_cnt[g];
    float p = 0.0f;
    if (cnt > 0.0f)
        p = g_scale[t] * g_pool[g * D + t] / cnt + g_shift[t];
    row[t] = p;
    __syncthreads();

    float a = lin1b[t];
    #pragma unroll 8
    for (int k = 0; k < D; k++) a += row[k] * lin1w[k * D + t];
    a = fmaxf(a, 0.0f);
    hid[t] = a;
    __syncthreads();

    if (t < N_CLASSES) {
        float o = lin2b[t];
        #pragma unroll 8
        for (int k = 0; k < D; k++) o += hid[k] * lin2w[k * N_CLASSES + t];
        out[g * N_CLASSES + t] = o;
    }
}

// ---------------------------------------------------------------------------
// Launcher
// ---------------------------------------------------------------------------
extern "C" void kernel_launch(void* const* d_in, const int* in_sizes, int n_in,
                              void* d_out, int out_size) {
    const float* x      = (const float*)d_in[0];
    const int*   ei     = (const int*)  d_in[1];
    const int*   batch  = (const int*)  d_in[2];
    const float* W1s    = (const float*)d_in[3];
    const float* b1s    = (const float*)d_in[4];
    const float* W2s    = (const float*)d_in[5];
    const float* b2s    = (const float*)d_in[6];
    const float* gammas = (const float*)d_in[7];
    const float* betas  = (const float*)d_in[8];
    const float* lin1w  = (const float*)d_in[9];
    const float* lin1b  = (const float*)d_in[10];
    const float* lin2w  = (const float*)d_in[11];
    const float* lin2b  = (const float*)d_in[12];
    float* out = (float*)d_out;

    const int* srcA = ei;
    const int* dstA = ei + N_EDGES;

    const size_t SMEM = (size_t)(D * D + 64 * 132 + 2 * D) * sizeof(float);
    cudaFuncSetAttribute(gemm_relu<0>,
                         cudaFuncAttributeMaxDynamicSharedMemorySize, (int)SMEM);
    cudaFuncSetAttribute(gemm_relu<1>,
                         cudaFuncAttributeMaxDynamicSharedMemorySize, (int)SMEM);

    void *pA, *pB;
    cudaGetSymbolAddress(&pA, g_bufA);
    cudaGetSymbolAddress(&pB, g_bufB);
    float* A = (float*)pA;
    float* B = (float*)pB;

    // CSR build (reused across layers)
    zero_deg_kernel<<<256, 256>>>();
    hist_kernel<<<2048, 256>>>(dstA);
    scan_kernel<<<1, 1024>>>();
    fill_kernel<<<2048, 256>>>(srcA, dstA);
    init_affine_kernel<<<1, 128>>>();

    const int AGG_BLOCKS  = (N_NODES + 7) / 8;          // 12500
    const int GEMM_BLOCKS = (N_NODES + 63) / 64;        // 1563

    const float* cur = x;
    for (int l = 0; l < N_LAYERS; l++) {
        aggregate_kernel<<<AGG_BLOCKS, 256>>>(cur, B);
        gemm_relu<0><<<GEMM_BLOCKS, 256, SMEM>>>(B, W1s + l * D * D,
                                                 b1s + l * D, A);
        zero_stats_kernel<<<1, 128>>>();
        gemm_relu<1><<<GEMM_BLOCKS, 256, SMEM>>>(A, W2s + l * D * D,
                                                 b2s + l * D, B);
        bn_finalize_kernel<<<1, 128>>>(gammas + l * D, betas + l * D);
        cur = B;
        float* tmp = A; A = B; B = tmp;
    }

    zero_pool_kernel<<<128, 256>>>();
    pool_kernel<<<AGG_BLOCKS, 256>>>(cur, batch);
    head_kernel<<<N_GRAPHS, 128>>>(lin1w, lin1b, lin2w, lin2b, out);
}